// round 2
// baseline (speedup 1.0000x reference)
#include <cuda_runtime.h>

// E8 quantizer, closed form (see Round-1 derivation).
//
// softmax over 240 E8 roots factorizes:
//  Type-1 (112): A_i = 2cosh(beta x_i), B_i = 2sinh(beta x_i)
//     weight sum = sum_{i<j} A_i A_j = 0.5 * sum_d A_d * exclSum_d(A)
//     numerator_d = B_d * exclSum_d(A)
//  Type-2 (128, even parity): a_i = 2cosh(beta x_i/2), b_i = 2sinh(beta x_i/2)
//     weight sum = (prod a + prod b)/2
//     numerator_d = ( b_d * exclProd_d(a) + a_d * exclProd_d(b) ) / 4
//  A = a^2 - 2, B = a*b  -> only 16 EX2 + 1 RCP per point.
//
// Exclusive sums/products via a binary TREE (up-sweep pairs/quads, down-sweep
// sibling products): all-positive adds and sign-safe muls only — no large-term
// subtraction, so no catastrophic cancellation when one exp dominates.
// Roots come in +- pairs => max dot >= 0 => denominator >= 1, no max-shift.
//
// 2 points per thread with all 4 LDG.128 issued up front (MLP=4) to cover
// DRAM + MUFU latency — Round-1 profile showed latency-bound (issue 57%,
// no pipe saturated).

#define BETA_HALF_LOG2E 4.8089834696568576f   // (2/0.3)/2 * log2(e)

__device__ __forceinline__ float ex2_approx(float x) {
    float y;
    asm("ex2.approx.ftz.f32 %0, %1;" : "=f"(y) : "f"(x));
    return y;
}

__device__ __forceinline__ float rcp_approx(float x) {
    float y;
    asm("rcp.approx.ftz.f32 %0, %1;" : "=f"(y) : "f"(x));
    return y;
}

__device__ __forceinline__ void e8_point(const float xi[8], float o[8]) {
    float a[8], b[8], A[8], B[8];
#pragma unroll
    for (int i = 0; i < 8; i++) {
        float t  = xi[i] * BETA_HALF_LOG2E;
        float hp = ex2_approx(t);
        float hn = ex2_approx(-t);
        a[i] = hp + hn;
        b[i] = hp - hn;
        A[i] = fmaf(a[i], a[i], -2.0f);
        B[i] = a[i] * b[i];
    }

    // ---- exclusive sums of A via tree (all positive) ----
    float s01 = A[0] + A[1], s23 = A[2] + A[3], s45 = A[4] + A[5], s67 = A[6] + A[7];
    float s0123 = s01 + s23, s4567 = s45 + s67;
    float ES0123 = s4567, ES4567 = s0123;
    float ES01 = ES0123 + s23, ES23 = ES0123 + s01;
    float ES45 = ES4567 + s67, ES67 = ES4567 + s45;
    float eS[8];
    eS[0] = ES01 + A[1]; eS[1] = ES01 + A[0];
    eS[2] = ES23 + A[3]; eS[3] = ES23 + A[2];
    eS[4] = ES45 + A[5]; eS[5] = ES45 + A[4];
    eS[6] = ES67 + A[7]; eS[7] = ES67 + A[6];

    // D1 = sum_{i<j} A_i A_j = 0.5 * sum_d A_d * eS_d
    float D1 = 0.0f;
#pragma unroll
    for (int d = 0; d < 8; d++) D1 = fmaf(A[d], eS[d], D1);
    D1 *= 0.5f;

    // ---- exclusive products of a (0.25 scale folded into tree root) ----
    float ma01 = a[0] * a[1], ma23 = a[2] * a[3], ma45 = a[4] * a[5], ma67 = a[6] * a[7];
    float ma0123 = ma01 * ma23, ma4567 = ma45 * ma67;
    float Pa = ma0123 * ma4567;                     // full product (unscaled)
    float EA0123 = ma4567 * 0.25f, EA4567 = ma0123 * 0.25f;
    float EA01 = EA0123 * ma23, EA23 = EA0123 * ma01;
    float EA45 = EA4567 * ma67, EA67 = EA4567 * ma45;
    float ea[8];
    ea[0] = EA01 * a[1]; ea[1] = EA01 * a[0];
    ea[2] = EA23 * a[3]; ea[3] = EA23 * a[2];
    ea[4] = EA45 * a[5]; ea[5] = EA45 * a[4];
    ea[6] = EA67 * a[7]; ea[7] = EA67 * a[6];

    // ---- exclusive products of b (0.25 folded) ----
    float mb01 = b[0] * b[1], mb23 = b[2] * b[3], mb45 = b[4] * b[5], mb67 = b[6] * b[7];
    float mb0123 = mb01 * mb23, mb4567 = mb45 * mb67;
    float Pb = mb0123 * mb4567;
    float EB0123 = mb4567 * 0.25f, EB4567 = mb0123 * 0.25f;
    float EB01 = EB0123 * mb23, EB23 = EB0123 * mb01;
    float EB45 = EB4567 * mb67, EB67 = EB4567 * mb45;
    float eb[8];
    eb[0] = EB01 * b[1]; eb[1] = EB01 * b[0];
    eb[2] = EB23 * b[3]; eb[3] = EB23 * b[2];
    eb[4] = EB45 * b[5]; eb[5] = EB45 * b[4];
    eb[6] = EB67 * b[7]; eb[7] = EB67 * b[6];

    float D  = fmaf(0.5f, Pa + Pb, D1);
    float rD = rcp_approx(D);

#pragma unroll
    for (int d = 0; d < 8; d++) {
        float inner = fmaf(b[d], ea[d], a[d] * eb[d]);   // carries the 1/4
        float num   = fmaf(B[d], eS[d], inner);
        o[d] = num * rD;
    }
}

__global__ void __launch_bounds__(256) e8_quantize_kernel(
    const float4* __restrict__ x4, float4* __restrict__ o4, int npair)
{
    int p = blockIdx.x * blockDim.x + threadIdx.x;   // thread handles points 2p, 2p+1
    if (p >= npair) return;

    // front-batch all 4 LDG.128 (MLP = 4)
    float4 v0 = x4[4 * p + 0];
    float4 v1 = x4[4 * p + 1];
    float4 v2 = x4[4 * p + 2];
    float4 v3 = x4[4 * p + 3];

    float xi0[8] = {v0.x, v0.y, v0.z, v0.w, v1.x, v1.y, v1.z, v1.w};
    float xi1[8] = {v2.x, v2.y, v2.z, v2.w, v3.x, v3.y, v3.z, v3.w};

    float o0[8], o1[8];
    e8_point(xi0, o0);
    e8_point(xi1, o1);

    o4[4 * p + 0] = make_float4(o0[0], o0[1], o0[2], o0[3]);
    o4[4 * p + 1] = make_float4(o0[4], o0[5], o0[6], o0[7]);
    o4[4 * p + 2] = make_float4(o1[0], o1[1], o1[2], o1[3]);
    o4[4 * p + 3] = make_float4(o1[4], o1[5], o1[6], o1[7]);
}

extern "C" void kernel_launch(void* const* d_in, const int* in_sizes, int n_in,
                              void* d_out, int out_size) {
    const float4* x4 = (const float4*)d_in[0];   // [N, 8] fp32
    float4* o4 = (float4*)d_out;
    int n = in_sizes[0] / 8;
    int npair = (n + 1) / 2;                     // N = 1M is even; guard anyway
    int block = 256;
    int grid = (npair + block - 1) / block;
    e8_quantize_kernel<<<grid, block>>>(x4, o4, npair);
}